// round 3
// baseline (speedup 1.0000x reference)
#include <cuda_runtime.h>

#define C_FEAT 64
#define NXc 432
#define NYc 496
#define S_CELLS (NXc * NYc)      // 214272 cells per batch element
#define SQ4 (S_CELLS / 4)        // float4 groups per batch/channel row
#define SQ8 (S_CELLS / 8)        // 8-cell groups per batch element
#define MAXB 8

// Scratch: cell -> local pillar index (uint16) map, 0xFFFF = empty.
// 8 * 214272 * 2B = 3.43 MB.
__device__ unsigned short g_map16[MAXB * S_CELLS];

__global__ void init_map_kernel(int n16) {   // n16 = #uint4 chunks (8 entries each)
    int i = blockIdx.x * blockDim.x + threadIdx.x;
    if (i < n16) {
        ((uint4*)g_map16)[i] = make_uint4(0xFFFFFFFFu, 0xFFFFFFFFu, 0xFFFFFFFFu, 0xFFFFFFFFu);
    }
}

__global__ void scatter_idx_kernel(const int* __restrict__ coords, int P, int Ppb, int ncells) {
    int p = blockIdx.x * blockDim.x + threadIdx.x;
    if (p >= P) return;
    int4 c = ((const int4*)coords)[p];   // (b, z, y, x) int32
    int flat = c.x * S_CELLS + c.y + c.z * NXc + c.w;
    int local = p - c.x * Ppb;           // per-batch pillar index
    if (flat >= 0 && flat < ncells && local >= 0 && local < 0xFFFF) {
        g_map16[flat] = (unsigned short)local;
    }
}

__global__ void __launch_bounds__(256) gather_kernel(
    const float4* __restrict__ feat4,   // [P, 16] float4
    float4* __restrict__ out4,          // [B, 64, S_CELLS/4] float4
    int total8, int Ppb)
{
    int t = blockIdx.x * blockDim.x + threadIdx.x;
    if (t >= total8) return;

    int b = t / SQ8;
    int q = t - b * SQ8;                 // 8-cell group within batch (cells 8q..8q+7)

    // One 16B load = 8 uint16 map entries (read-once: streaming)
    uint4 mraw = __ldcs(((const uint4*)(g_map16 + b * S_CELLS)) + q);
    unsigned m[8];
    m[0] = mraw.x & 0xFFFFu;  m[1] = mraw.x >> 16;
    m[2] = mraw.y & 0xFFFFu;  m[3] = mraw.y >> 16;
    m[4] = mraw.z & 0xFFFFu;  m[5] = mraw.z >> 16;
    m[6] = mraw.w & 0xFFFFu;  m[7] = mraw.w >> 16;

    const float4* fr[8];
    size_t pbase = (size_t)b * (size_t)Ppb;
#pragma unroll
    for (int j = 0; j < 8; ++j)
        fr[j] = feat4 + (pbase + m[j]) * (C_FEAT / 4);

    // Output: channel c row for this batch starts at b*64*SQ4 + c*SQ4;
    // this thread's 8 cells occupy float4 slots 2q and 2q+1 in each row.
    float4* o = out4 + (size_t)b * C_FEAT * SQ4 + 2 * (size_t)q;

    const float4 z4 = make_float4(0.f, 0.f, 0.f, 0.f);

#pragma unroll 4
    for (int c4 = 0; c4 < C_FEAT / 4; ++c4) {
        float4 r[8];
#pragma unroll
        for (int j = 0; j < 8; ++j)
            r[j] = (m[j] != 0xFFFFu) ? __ldcs(fr[j] + c4) : z4;

        // 8-wide transpose: for each of 4 channels emit 2 contiguous float4
#pragma unroll
        for (int cc = 0; cc < 4; ++cc) {
            const float* s0 = (const float*)&r[0];
            float4 lo = make_float4(((const float*)&r[0])[cc], ((const float*)&r[1])[cc],
                                    ((const float*)&r[2])[cc], ((const float*)&r[3])[cc]);
            float4 hi = make_float4(((const float*)&r[4])[cc], ((const float*)&r[5])[cc],
                                    ((const float*)&r[6])[cc], ((const float*)&r[7])[cc]);
            float4* orow = o + (size_t)(4 * c4 + cc) * SQ4;
            __stcs(orow,     lo);
            __stcs(orow + 1, hi);
            (void)s0;
        }
    }
}

extern "C" void kernel_launch(void* const* d_in, const int* in_sizes, int n_in,
                              void* d_out, int out_size) {
    const float* feat   = (const float*)d_in[0];
    const int*   coords = (const int*)d_in[1];

    int P = in_sizes[0] / C_FEAT;                 // number of pillars
    int B = out_size / (C_FEAT * S_CELLS);        // batch size from output shape
    if (B > MAXB) B = MAXB;
    int Ppb = P / B;

    int ncells = B * S_CELLS;
    int n16 = ncells / 8;                         // uint4 chunks of 8 uint16
    init_map_kernel<<<(n16 + 255) / 256, 256>>>(n16);
    scatter_idx_kernel<<<(P + 255) / 256, 256>>>(coords, P, Ppb, ncells);

    int total8 = B * SQ8;
    gather_kernel<<<(total8 + 255) / 256, 256>>>(
        (const float4*)feat, (float4*)d_out, total8, Ppb);
}

// round 5
// speedup vs baseline: 1.4998x; 1.4998x over previous
#include <cuda_runtime.h>

#define C_FEAT 64
#define NXc 432
#define NYc 496
#define S_CELLS (NXc * NYc)      // 214272 cells per batch element
#define SQ4 (S_CELLS / 4)        // float4 groups per batch/channel row
#define MAXB 8

// Scratch: cell -> local pillar index (uint16) map, 0xFFFF = empty.
// 8 * 214272 * 2B = 3.43 MB.
__device__ unsigned short g_map16[MAXB * S_CELLS];

__global__ void init_map_kernel(int n16) {   // n16 = #uint4 chunks (8 entries each)
    int i = blockIdx.x * blockDim.x + threadIdx.x;
    if (i < n16) {
        ((uint4*)g_map16)[i] = make_uint4(0xFFFFFFFFu, 0xFFFFFFFFu, 0xFFFFFFFFu, 0xFFFFFFFFu);
    }
}

__global__ void scatter_idx_kernel(const int* __restrict__ coords, int P, int Ppb, int ncells) {
    int p = blockIdx.x * blockDim.x + threadIdx.x;
    if (p >= P) return;
    int4 c = ((const int4*)coords)[p];   // (b, z, y, x) int32
    int flat = c.x * S_CELLS + c.y + c.z * NXc + c.w;
    int local = p - c.x * Ppb;           // per-batch pillar index
    if (flat >= 0 && flat < ncells && local >= 0 && local < 0xFFFF) {
        g_map16[flat] = (unsigned short)local;
    }
}

__global__ void __launch_bounds__(256) gather_kernel(
    const float* __restrict__ feat,     // [P, 64]
    float4* __restrict__ out4,          // [B, 64, S_CELLS/4] float4
    int total4, int Ppb)
{
    int t = blockIdx.x * blockDim.x + threadIdx.x;
    if (t >= total4) return;

    int b = t / SQ4;
    int q = t - b * SQ4;                 // float4-group within batch: 4 consecutive x-cells

    // One 8B load = 4 uint16 map entries
    uint2 mraw = ((const uint2*)(g_map16 + b * S_CELLS))[q];
    unsigned m0 = mraw.x & 0xFFFFu, m1 = mraw.x >> 16;
    unsigned m2 = mraw.y & 0xFFFFu, m3 = mraw.y >> 16;

    size_t pbase = (size_t)b * (size_t)Ppb;
    const float4* f0 = (const float4*)(feat + (pbase + m0) * C_FEAT);
    const float4* f1 = (const float4*)(feat + (pbase + m1) * C_FEAT);
    const float4* f2 = (const float4*)(feat + (pbase + m2) * C_FEAT);
    const float4* f3 = (const float4*)(feat + (pbase + m3) * C_FEAT);

    float4* o = out4 + (size_t)b * C_FEAT * SQ4 + q;

    const float4 z4 = make_float4(0.f, 0.f, 0.f, 0.f);

#pragma unroll
    for (int c4 = 0; c4 < C_FEAT / 4; ++c4) {
        // plain derefs -> compiler emits predicated LDG (no branches)
        float4 a  = (m0 != 0xFFFFu) ? f0[c4] : z4;
        float4 bb = (m1 != 0xFFFFu) ? f1[c4] : z4;
        float4 cc = (m2 != 0xFFFFu) ? f2[c4] : z4;
        float4 dd = (m3 != 0xFFFFu) ? f3[c4] : z4;

        // 4x4 register transpose: channel-major, coalesced, streaming stores
        __stcs(o + (size_t)(4 * c4 + 0) * SQ4, make_float4(a.x, bb.x, cc.x, dd.x));
        __stcs(o + (size_t)(4 * c4 + 1) * SQ4, make_float4(a.y, bb.y, cc.y, dd.y));
        __stcs(o + (size_t)(4 * c4 + 2) * SQ4, make_float4(a.z, bb.z, cc.z, dd.z));
        __stcs(o + (size_t)(4 * c4 + 3) * SQ4, make_float4(a.w, bb.w, cc.w, dd.w));
    }
}

extern "C" void kernel_launch(void* const* d_in, const int* in_sizes, int n_in,
                              void* d_out, int out_size) {
    const float* feat   = (const float*)d_in[0];
    const int*   coords = (const int*)d_in[1];

    int P = in_sizes[0] / C_FEAT;                 // number of pillars
    int B = out_size / (C_FEAT * S_CELLS);        // batch size from output shape
    if (B > MAXB) B = MAXB;
    int Ppb = P / B;

    int ncells = B * S_CELLS;
    int n16 = ncells / 8;                         // uint4 chunks of 8 uint16
    init_map_kernel<<<(n16 + 255) / 256, 256>>>(n16);
    scatter_idx_kernel<<<(P + 255) / 256, 256>>>(coords, P, Ppb, ncells);

    int total4 = B * SQ4;
    gather_kernel<<<(total4 + 255) / 256, 256>>>(feat, (float4*)d_out, total4, Ppb);
}

// round 6
// speedup vs baseline: 1.5480x; 1.0321x over previous
#include <cuda_runtime.h>

#define C_FEAT 64
#define NXc 432
#define NYc 496
#define S_CELLS (NXc * NYc)      // 214272 cells per batch element
#define SQ4 (S_CELLS / 4)        // float4 groups per batch/channel row
#define MAXB 8

// Scratch: cell -> (local pillar index + 1), 0 = empty.
// Zero-initialized at module load; gather_kernel restores zeros after use,
// so the empty-map invariant holds before every kernel_launch call.
__device__ unsigned short g_map16[MAXB * S_CELLS];

__global__ void scatter_idx_kernel(const int* __restrict__ coords, int P, int Ppb, int ncells) {
    int p = blockIdx.x * blockDim.x + threadIdx.x;
    if (p >= P) return;
    int4 c = ((const int4*)coords)[p];   // (b, z, y, x) int32
    int flat = c.x * S_CELLS + c.y + c.z * NXc + c.w;
    int local = p - c.x * Ppb;           // per-batch pillar index
    if (flat >= 0 && flat < ncells && local >= 0 && local < 0xFFFF) {
        g_map16[flat] = (unsigned short)(local + 1);
    }
}

__global__ void __launch_bounds__(256) gather_kernel(
    const float* __restrict__ feat,     // [P, 64]
    float4* __restrict__ out4,          // [B, 64, S_CELLS/4] float4
    int total4, int Ppb)
{
    int t = blockIdx.x * blockDim.x + threadIdx.x;
    if (t >= total4) return;

    int b = t / SQ4;
    int q = t - b * SQ4;                 // float4-group within batch: 4 consecutive x-cells

    // One 8B load = 4 uint16 map entries (0 = empty, else local+1)
    uint2* mp = ((uint2*)(g_map16 + b * S_CELLS)) + q;
    uint2 mraw = *mp;
    // Reset to empty for the next invocation (only where needed)
    if (mraw.x | mraw.y) {
        *mp = make_uint2(0u, 0u);
    }

    unsigned m0 = mraw.x & 0xFFFFu, m1 = mraw.x >> 16;
    unsigned m2 = mraw.y & 0xFFFFu, m3 = mraw.y >> 16;

    size_t pbase = (size_t)b * (size_t)Ppb;
    const float4* f0 = (const float4*)(feat + (pbase + m0 - 1) * C_FEAT);
    const float4* f1 = (const float4*)(feat + (pbase + m1 - 1) * C_FEAT);
    const float4* f2 = (const float4*)(feat + (pbase + m2 - 1) * C_FEAT);
    const float4* f3 = (const float4*)(feat + (pbase + m3 - 1) * C_FEAT);

    float4* o = out4 + (size_t)b * C_FEAT * SQ4 + q;

    const float4 z4 = make_float4(0.f, 0.f, 0.f, 0.f);

#pragma unroll
    for (int c4 = 0; c4 < C_FEAT / 4; ++c4) {
        // plain derefs -> compiler emits predicated LDG (no branches)
        float4 a  = (m0 != 0u) ? f0[c4] : z4;
        float4 bb = (m1 != 0u) ? f1[c4] : z4;
        float4 cc = (m2 != 0u) ? f2[c4] : z4;
        float4 dd = (m3 != 0u) ? f3[c4] : z4;

        // 4x4 register transpose: channel-major, coalesced, streaming stores
        __stcs(o + (size_t)(4 * c4 + 0) * SQ4, make_float4(a.x, bb.x, cc.x, dd.x));
        __stcs(o + (size_t)(4 * c4 + 1) * SQ4, make_float4(a.y, bb.y, cc.y, dd.y));
        __stcs(o + (size_t)(4 * c4 + 2) * SQ4, make_float4(a.z, bb.z, cc.z, dd.z));
        __stcs(o + (size_t)(4 * c4 + 3) * SQ4, make_float4(a.w, bb.w, cc.w, dd.w));
    }
}

extern "C" void kernel_launch(void* const* d_in, const int* in_sizes, int n_in,
                              void* d_out, int out_size) {
    const float* feat   = (const float*)d_in[0];
    const int*   coords = (const int*)d_in[1];

    int P = in_sizes[0] / C_FEAT;                 // number of pillars
    int B = out_size / (C_FEAT * S_CELLS);        // batch size from output shape
    if (B > MAXB) B = MAXB;
    int Ppb = P / B;

    int ncells = B * S_CELLS;
    scatter_idx_kernel<<<(P + 255) / 256, 256>>>(coords, P, Ppb, ncells);

    int total4 = B * SQ4;
    gather_kernel<<<(total4 + 255) / 256, 256>>>(feat, (float4*)d_out, total4, Ppb);
}

// round 7
// speedup vs baseline: 1.6292x; 1.0524x over previous
#include <cuda_runtime.h>

#define C_FEAT 64
#define NXc 432
#define NYc 496
#define S_CELLS (NXc * NYc)      // 214272 cells per batch element
#define SQ4 (S_CELLS / 4)        // float4 groups per batch/channel row (53568, divisible by 64)
#define MAXB 8

// Scratch: cell -> (local pillar index + 1), 0 = empty.
// Zero-initialized at module load; gather_kernel restores zeros after use,
// so the empty-map invariant holds before every kernel_launch call.
__device__ unsigned short g_map16[MAXB * S_CELLS];

__global__ void scatter_idx_kernel(const int* __restrict__ coords, int P, int Ppb, int ncells) {
    int p = blockIdx.x * blockDim.x + threadIdx.x;
    if (p >= P) return;
    int4 c = ((const int4*)coords)[p];   // (b, z, y, x) int32
    int flat = c.x * S_CELLS + c.y + c.z * NXc + c.w;
    int local = p - c.x * Ppb;           // per-batch pillar index
    if (flat >= 0 && flat < ncells && local >= 0 && local < 0xFFFF) {
        g_map16[flat] = (unsigned short)(local + 1);
    }
}

// Block (64, 4): x = spatial float4-group, y = channel slice (16 channels each).
// Grid covers B*SQ4 exactly (SQ4 % 64 == 0) -> no bounds checks.
__global__ void __launch_bounds__(256) gather_kernel(
    const float* __restrict__ feat,     // [P, 64]
    float4* __restrict__ out4,          // [B, 64, S_CELLS/4] float4
    int Ppb)
{
    int t = blockIdx.x * 64 + threadIdx.x;   // global q-group index
    int s = threadIdx.y;                     // channel slice 0..3

    int b = t / SQ4;
    int q = t - b * SQ4;

    // One 8B load = 4 uint16 map entries (0 = empty, else local+1)
    uint2* mp = ((uint2*)(g_map16 + b * S_CELLS)) + q;
    uint2 mraw = *mp;

    // All 4 slices have read this entry before slice 0 resets it.
    __syncthreads();
    if (s == 0 && (mraw.x | mraw.y)) {
        *mp = make_uint2(0u, 0u);
    }

    unsigned m0 = mraw.x & 0xFFFFu, m1 = mraw.x >> 16;
    unsigned m2 = mraw.y & 0xFFFFu, m3 = mraw.y >> 16;

    size_t pbase = (size_t)b * (size_t)Ppb;
    const float4* f0 = (const float4*)(feat + (pbase + m0 - 1) * C_FEAT);
    const float4* f1 = (const float4*)(feat + (pbase + m1 - 1) * C_FEAT);
    const float4* f2 = (const float4*)(feat + (pbase + m2 - 1) * C_FEAT);
    const float4* f3 = (const float4*)(feat + (pbase + m3 - 1) * C_FEAT);

    float4* o = out4 + (size_t)b * C_FEAT * SQ4 + q;

    const float4 z4 = make_float4(0.f, 0.f, 0.f, 0.f);

#pragma unroll
    for (int i = 0; i < 4; ++i) {
        int c4 = 4 * s + i;                 // this slice's float4-channel-group
        // plain derefs -> predicated LDG (no branches)
        float4 a  = (m0 != 0u) ? f0[c4] : z4;
        float4 bb = (m1 != 0u) ? f1[c4] : z4;
        float4 cc = (m2 != 0u) ? f2[c4] : z4;
        float4 dd = (m3 != 0u) ? f3[c4] : z4;

        // 4x4 register transpose: warp writes 32 consecutive float4 per row (512B)
        __stcs(o + (size_t)(4 * c4 + 0) * SQ4, make_float4(a.x, bb.x, cc.x, dd.x));
        __stcs(o + (size_t)(4 * c4 + 1) * SQ4, make_float4(a.y, bb.y, cc.y, dd.y));
        __stcs(o + (size_t)(4 * c4 + 2) * SQ4, make_float4(a.z, bb.z, cc.z, dd.z));
        __stcs(o + (size_t)(4 * c4 + 3) * SQ4, make_float4(a.w, bb.w, cc.w, dd.w));
    }
}

extern "C" void kernel_launch(void* const* d_in, const int* in_sizes, int n_in,
                              void* d_out, int out_size) {
    const float* feat   = (const float*)d_in[0];
    const int*   coords = (const int*)d_in[1];

    int P = in_sizes[0] / C_FEAT;                 // number of pillars
    int B = out_size / (C_FEAT * S_CELLS);        // batch size from output shape
    if (B > MAXB) B = MAXB;
    int Ppb = P / B;

    int ncells = B * S_CELLS;
    scatter_idx_kernel<<<(P + 255) / 256, 256>>>(coords, P, Ppb, ncells);

    dim3 blk(64, 4);
    int nblocks = (B * SQ4) / 64;                 // exact: SQ4 % 64 == 0
    gather_kernel<<<nblocks, blk>>>(feat, (float4*)d_out, Ppb);
}